// round 2
// baseline (speedup 1.0000x reference)
#include <cuda_runtime.h>
#include <cstdint>

using ull = unsigned long long;

#define VOC 95
#define TT  256
#define NW  4     // warps per block
#define NB  128   // blocks

// shared layout (float offsets)
#define OFF_W1I 0        // [3][24][32][4] = 9216
#define OFF_W1H 9216     // [3][8][32][4]  = 3072
#define OFF_W2I 12288
#define OFF_W2H 15360
#define OFF_W3I 18432
#define OFF_W3H 21504
#define OFF_WFC 24576    // 3072
#define OFF_XS  27648    // float2 xs[4 warps][2 buf][2 pair][96]  = 3072 floats
#define OFF_HS  30720    // float2 hs[4 warps][3 layer][2 pair][32] = 1536 floats
#define SMEM_FLOATS 32256
#define SMEM_BYTES  (SMEM_FLOATS * 4)

extern __shared__ float smem[];

// ---------- packed fp32x2 helpers ----------
__device__ __forceinline__ ull pk2(float w) {
    ull d; unsigned r = __float_as_uint(w);
    asm("mov.b64 %0, {%1,%1};" : "=l"(d) : "r"(r));
    return d;
}
__device__ __forceinline__ ull pkf(float a, float b) {
    ull d;
    asm("mov.b64 %0, {%1,%2};" : "=l"(d)
        : "r"(__float_as_uint(a)), "r"(__float_as_uint(b)));
    return d;
}
__device__ __forceinline__ float2 up2(ull v) {
    unsigned lo, hi;
    asm("mov.b64 {%0,%1}, %2;" : "=r"(lo), "=r"(hi) : "l"(v));
    return make_float2(__uint_as_float(lo), __uint_as_float(hi));
}
__device__ __forceinline__ void fma2(ull& d, ull a, ull b) {
    asm("fma.rn.f32x2 %0, %1, %2, %0;" : "+l"(d) : "l"(a), "l"(b));
}
__device__ __forceinline__ ull add2(ull a, ull b) {
    ull d; asm("add.rn.f32x2 %0, %1, %2;" : "=l"(d) : "l"(a), "l"(b));
    return d;
}

// ---------- activations ----------
__device__ __forceinline__ float fsig(float v) {
    return __fdividef(1.f, 1.f + __expf(-v));
}
__device__ __forceinline__ float ftanh_(float v) {
    return 1.f - __fdividef(2.f, __expf(2.f * v) + 1.f);
}

// ---------- 3-gate projection over C 4-wide input chunks, 2 packed pairs ----------
// W layout: [gate(3)][chunk(C)][lane(32)][4], lane j owns output unit j of each gate.
// in0/in1: float2[4*C] arrays, element i = (rowEven_i, rowOdd_i) of the pair.
template<int C>
__device__ __forceinline__ void proj3(const float* __restrict__ W, int j,
                                      const float2* __restrict__ in0,
                                      const float2* __restrict__ in1,
                                      ull& aA0, ull& aB0, ull& aC0,
                                      ull& aA1, ull& aB1, ull& aC1)
{
#pragma unroll 4
    for (int c = 0; c < C; c++) {
        float4 wA = *(const float4*)(W + ((0 * C + c) * 32 + j) * 4);
        float4 wB = *(const float4*)(W + ((1 * C + c) * 32 + j) * 4);
        float4 wC = *(const float4*)(W + ((2 * C + c) * 32 + j) * 4);
        ulonglong2 x01 = *(const ulonglong2*)(in0 + 4 * c);
        ulonglong2 x23 = *(const ulonglong2*)(in0 + 4 * c + 2);
        ulonglong2 y01 = *(const ulonglong2*)(in1 + 4 * c);
        ulonglong2 y23 = *(const ulonglong2*)(in1 + 4 * c + 2);
        ull w;
        w = pk2(wA.x); fma2(aA0, x01.x, w); fma2(aA1, y01.x, w);
        w = pk2(wA.y); fma2(aA0, x01.y, w); fma2(aA1, y01.y, w);
        w = pk2(wA.z); fma2(aA0, x23.x, w); fma2(aA1, y23.x, w);
        w = pk2(wA.w); fma2(aA0, x23.y, w); fma2(aA1, y23.y, w);
        w = pk2(wB.x); fma2(aB0, x01.x, w); fma2(aB1, y01.x, w);
        w = pk2(wB.y); fma2(aB0, x01.y, w); fma2(aB1, y01.y, w);
        w = pk2(wB.z); fma2(aB0, x23.x, w); fma2(aB1, y23.x, w);
        w = pk2(wB.w); fma2(aB0, x23.y, w); fma2(aB1, y23.y, w);
        w = pk2(wC.x); fma2(aC0, x01.x, w); fma2(aC1, y01.x, w);
        w = pk2(wC.y); fma2(aC0, x01.y, w); fma2(aC1, y01.y, w);
        w = pk2(wC.z); fma2(aC0, x23.x, w); fma2(aC1, y23.x, w);
        w = pk2(wC.w); fma2(aC0, x23.y, w); fma2(aC1, y23.y, w);
    }
}

// ---------- GRU elementwise for one packed row-pair ----------
__device__ __forceinline__ ull gru_pair(ull aR, ull aZ, ull aNx, ull aNh, ull h)
{
    float2 r2 = up2(aR), z2 = up2(aZ), nx = up2(aNx), nh = up2(aNh), hh = up2(h);
    float r0 = fsig(r2.x), r1 = fsig(r2.y);
    float z0 = fsig(z2.x), z1 = fsig(z2.y);
    float n0 = ftanh_(nx.x + r0 * nh.x);
    float n1 = ftanh_(nx.y + r1 * nh.y);
    float h0 = n0 + z0 * (hh.x - n0);
    float h1 = n1 + z1 * (hh.y - n1);
    return pkf(h0, h1);
}

// One GRU layer step for this warp's 2 row-pairs.
// hbuf: float2[2][32] for this layer (pair0 at hbuf, pair1 at hbuf+32).
template<int C>
__device__ __forceinline__ void layer_step(const float* __restrict__ Wi,
                                           const float* __restrict__ Wh,
                                           const float2* __restrict__ in0,
                                           const float2* __restrict__ in1,
                                           float2* hbuf, int j,
                                           ull biR, ull biZ, ull biN,
                                           ull bhR, ull bhZ, ull bhN)
{
    ull xR0 = biR, xZ0 = biZ, xN0 = biN, xR1 = biR, xZ1 = biZ, xN1 = biN;
    proj3<C>(Wi, j, in0, in1, xR0, xZ0, xN0, xR1, xZ1, xN1);
    ull hR0 = bhR, hZ0 = bhZ, hN0 = bhN, hR1 = bhR, hZ1 = bhZ, hN1 = bhN;
    proj3<8>(Wh, j, hbuf, hbuf + 32, hR0, hZ0, hN0, hR1, hZ1, hN1);
    ull h0 = *(const ull*)(hbuf + j);
    ull h1 = *(const ull*)(hbuf + 32 + j);
    __syncwarp();   // all lanes done reading old h before overwrite
    ull n0 = gru_pair(add2(xR0, hR0), add2(xZ0, hZ0), xN0, hN0, h0);
    ull n1 = gru_pair(add2(xR1, hR1), add2(xZ1, hZ1), xN1, hN1, h1);
    *(ull*)(hbuf + j) = n0;
    *(ull*)(hbuf + 32 + j) = n1;
    __syncwarp();   // new h visible to all lanes
}

// GMEM weight [3*32, isz] -> SMEM [g][c][lane][4] (i >= isz zero-padded)
__device__ __forceinline__ void load_wmat(float* dst, const float* __restrict__ src,
                                          int C, int isz, int tid)
{
    int n = 3 * C * 128;
    for (int idx = tid; idx < n; idx += 128) {
        int q = idx & 3, jj = (idx >> 2) & 31;
        int c = (idx >> 7) % C, g = idx / (C * 128);
        int i = c * 4 + q;
        dst[idx] = (i < isz) ? src[(g * 32 + jj) * isz + i] : 0.f;
    }
}

__global__ void __launch_bounds__(128)
gru_fused(const float* __restrict__ x,
          const float* __restrict__ Wih1, const float* __restrict__ Whh1,
          const float* __restrict__ bih1, const float* __restrict__ bhh1,
          const float* __restrict__ Wih2, const float* __restrict__ Whh2,
          const float* __restrict__ bih2, const float* __restrict__ bhh2,
          const float* __restrict__ Wih3, const float* __restrict__ Whh3,
          const float* __restrict__ bih3, const float* __restrict__ bhh3,
          const float* __restrict__ Wfc,  const float* __restrict__ bfc,
          float* __restrict__ out)
{
    const int tid = threadIdx.x;

    // ---- cooperative weight permute into SMEM ----
    load_wmat(smem + OFF_W1I, Wih1, 24, VOC, tid);
    load_wmat(smem + OFF_W1H, Whh1, 8, 32, tid);
    load_wmat(smem + OFF_W2I, Wih2, 8, 32, tid);
    load_wmat(smem + OFF_W2H, Whh2, 8, 32, tid);
    load_wmat(smem + OFF_W3I, Wih3, 8, 32, tid);
    load_wmat(smem + OFF_W3H, Whh3, 8, 32, tid);
    {   // FC: output o = g*32+j (pad o=95), input k = c*4+q; src Wfc[o*32+k]
        float* dst = smem + OFF_WFC;
        for (int idx = tid; idx < 3 * 8 * 128; idx += 128) {
            int q = idx & 3, jj = (idx >> 2) & 31;
            int c = (idx >> 7) % 8, g = idx / (8 * 128);
            int o = g * 32 + jj, k = c * 4 + q;
            dst[idx] = (o < VOC) ? Wfc[o * 32 + k] : 0.f;
        }
    }
    // zero x-stage + h-stage (h0 = 0; xs[95] stays 0 forever)
    for (int idx = tid; idx < SMEM_FLOATS - OFF_XS; idx += 128)
        smem[OFF_XS + idx] = 0.f;
    __syncthreads();

    const int w = tid >> 5, j = tid & 31;
    const int gw = blockIdx.x * NW + w;
    const int rb = gw * 4;             // 4 batch rows per warp

    float2* xsw = (float2*)(smem + OFF_XS) + (size_t)w * (2 * 2 * 96);
    float2* hsw = (float2*)(smem + OFF_HS) + (size_t)w * (3 * 2 * 32);

    // per-lane bias packs
    ull bi1R = pk2(bih1[j]),      bi1Z = pk2(bih1[32 + j]), bi1N = pk2(bih1[64 + j]);
    ull bh1R = pk2(bhh1[j]),      bh1Z = pk2(bhh1[32 + j]), bh1N = pk2(bhh1[64 + j]);
    ull bi2R = pk2(bih2[j]),      bi2Z = pk2(bih2[32 + j]), bi2N = pk2(bih2[64 + j]);
    ull bh2R = pk2(bhh2[j]),      bh2Z = pk2(bhh2[32 + j]), bh2N = pk2(bhh2[64 + j]);
    ull bi3R = pk2(bih3[j]),      bi3Z = pk2(bih3[32 + j]), bi3N = pk2(bih3[64 + j]);
    ull bh3R = pk2(bhh3[j]),      bh3Z = pk2(bhh3[32 + j]), bh3N = pk2(bhh3[64 + j]);
    float bf0 = (j      < VOC) ? bfc[j]      : 0.f;
    float bf1 = (32 + j < VOC) ? bfc[32 + j] : 0.f;
    float bf2 = (64 + j < VOC) ? bfc[64 + j] : 0.f;
    ull bfc0 = pk2(bf0), bfc1 = pk2(bf1), bfc2 = pk2(bf2);

    // ---- prologue: stage x[t=0] into buffer 0 ----
#pragma unroll
    for (int p = 0; p < 2; p++)
#pragma unroll
        for (int k = 0; k < 3; k++) {
            int i = j + 32 * k;
            if (i < VOC) {
                float a = x[((size_t)(rb + 2 * p)     * TT + 0) * VOC + i];
                float b = x[((size_t)(rb + 2 * p + 1) * TT + 0) * VOC + i];
                xsw[(size_t)p * 96 + i] = make_float2(a, b);
            }
        }
    __syncwarp();

#pragma unroll 1
    for (int t = 0; t < TT; t++) {
        // prefetch x[t+1] into registers (latency hidden by compute)
        float pa[2][3], pb[2][3];
        const int tn = t + 1;
        if (tn < TT) {
#pragma unroll
            for (int p = 0; p < 2; p++)
#pragma unroll
                for (int k = 0; k < 3; k++) {
                    int i = j + 32 * k;
                    if (i < VOC) {
                        pa[p][k] = x[((size_t)(rb + 2 * p)     * TT + tn) * VOC + i];
                        pb[p][k] = x[((size_t)(rb + 2 * p + 1) * TT + tn) * VOC + i];
                    } else { pa[p][k] = 0.f; pb[p][k] = 0.f; }
                }
        }

        const float2* xb = xsw + (size_t)((t & 1) * 2) * 96;

        layer_step<24>(smem + OFF_W1I, smem + OFF_W1H, xb, xb + 96,
                       hsw + 0, j, bi1R, bi1Z, bi1N, bh1R, bh1Z, bh1N);
        layer_step<8>(smem + OFF_W2I, smem + OFF_W2H, hsw + 0, hsw + 32,
                       hsw + 64, j, bi2R, bi2Z, bi2N, bh2R, bh2Z, bh2N);
        layer_step<8>(smem + OFF_W3I, smem + OFF_W3H, hsw + 64, hsw + 96,
                       hsw + 128, j, bi3R, bi3Z, bi3N, bh3R, bh3Z, bh3N);

        // FC head: out = h3 @ Wfc^T + bfc, three 32-wide output groups
        {
            ull a00 = bfc0, a10 = bfc1, a20 = bfc2;
            ull a01 = bfc0, a11 = bfc1, a21 = bfc2;
            proj3<8>(smem + OFF_WFC, j, hsw + 128, hsw + 160,
                     a00, a10, a20, a01, a11, a21);
            float2 v;
            size_t base0 = ((size_t)(rb + 0) * TT + t) * VOC;
            size_t base1 = ((size_t)(rb + 1) * TT + t) * VOC;
            size_t base2 = ((size_t)(rb + 2) * TT + t) * VOC;
            size_t base3 = ((size_t)(rb + 3) * TT + t) * VOC;
            int o0 = j, o1 = 32 + j, o2 = 64 + j;
            v = up2(a00); out[base0 + o0] = v.x; out[base1 + o0] = v.y;
            v = up2(a01); out[base2 + o0] = v.x; out[base3 + o0] = v.y;
            v = up2(a10); out[base0 + o1] = v.x; out[base1 + o1] = v.y;
            v = up2(a11); out[base2 + o1] = v.x; out[base3 + o1] = v.y;
            if (o2 < VOC) {
                v = up2(a20); out[base0 + o2] = v.x; out[base1 + o2] = v.y;
                v = up2(a21); out[base2 + o2] = v.x; out[base3 + o2] = v.y;
            }
        }

        // stage prefetched x[t+1] into the other buffer
        if (tn < TT) {
            float2* nb = xsw + (size_t)((tn & 1) * 2) * 96;
#pragma unroll
            for (int p = 0; p < 2; p++)
#pragma unroll
                for (int k = 0; k < 3; k++) {
                    int i = j + 32 * k;
                    if (i < VOC)
                        nb[(size_t)p * 96 + i] = make_float2(pa[p][k], pb[p][k]);
                }
        }
        __syncwarp();
    }
}

extern "C" void kernel_launch(void* const* d_in, const int* in_sizes, int n_in,
                              void* d_out, int out_size)
{
    const float* x    = (const float*)d_in[0];
    const float* Wih1 = (const float*)d_in[1];
    const float* Whh1 = (const float*)d_in[2];
    const float* bih1 = (const float*)d_in[3];
    const float* bhh1 = (const float*)d_in[4];
    const float* Wih2 = (const float*)d_in[5];
    const float* Whh2 = (const float*)d_in[6];
    const float* bih2 = (const float*)d_in[7];
    const float* bhh2 = (const float*)d_in[8];
    const float* Wih3 = (const float*)d_in[9];
    const float* Whh3 = (const float*)d_in[10];
    const float* bih3 = (const float*)d_in[11];
    const float* bhh3 = (const float*)d_in[12];
    const float* Wfc  = (const float*)d_in[13];
    const float* bfc  = (const float*)d_in[14];
    float* out = (float*)d_out;

    cudaFuncSetAttribute(gru_fused, cudaFuncAttributeMaxDynamicSharedMemorySize,
                         SMEM_BYTES);
    gru_fused<<<NB, 128, SMEM_BYTES>>>(x, Wih1, Whh1, bih1, bhh1,
                                       Wih2, Whh2, bih2, bhh2,
                                       Wih3, Whh3, bih3, bhh3,
                                       Wfc, bfc, out);
}